// round 3
// baseline (speedup 1.0000x reference)
#include <cuda_runtime.h>
#include <stdint.h>

// ---------------- problem constants ----------------
#define MAXM      300000
#define NCLS      80
#define TOPK      1000
#define CONF      0.001f
#define NMSTH     0.5f
#define CLSOFF    4096.0f
#define CAND_CAP  4096
#define NBINS     4096
#define SUPSTRIDE 1025     // 32 words x 1025 stride -> conflict-free rows & cols

// ---------------- device scratch (zero-initialized at load) ----------------
__device__ uint32_t g_scorebits[MAXM];
__device__ uint8_t  g_label[MAXM];
__device__ uint32_t g_hist[NBINS];   // returned to all-zero by each consumer
__device__ uint32_t g_prefix;
__device__ uint32_t g_need;
__device__ uint32_t g_cand_cnt;
__device__ uint32_t g_tick1, g_tick2, g_tick3;
__device__ unsigned long long g_cand[CAND_CAP];

__device__ __forceinline__ float sigf(float x) {
    return 1.0f / (1.0f + expf(-x));
}

// ============================================================================
// K1: fused score + argmax label + 12-bit hist; LAST BLOCK: round-1 select
// ============================================================================
__global__ void k_score(const float* __restrict__ obj,
                        const float* __restrict__ cls, int M) {
    __shared__ uint32_t sh[NBINS];
    for (int i = threadIdx.x; i < NBINS; i += blockDim.x) sh[i] = 0;
    __syncthreads();

    int m = blockIdx.x * blockDim.x + threadIdx.x;
    if (m < M) {
        const float4* c4 = (const float4*)(cls + (size_t)m * NCLS);
        float best = -1e30f;
        int lab = 0;
#pragma unroll
        for (int q = 0; q < NCLS / 4; q++) {
            float4 v = c4[q];
            if (v.x > best) { best = v.x; lab = q * 4 + 0; }
            if (v.y > best) { best = v.y; lab = q * 4 + 1; }
            if (v.z > best) { best = v.z; lab = q * 4 + 2; }
            if (v.w > best) { best = v.w; lab = q * 4 + 3; }
        }
        // monotone: max_c sqrt(sig(o)*sig(c)) == sqrt(sig(o)*sig(max_c))
        float f = sqrtf(sigf(obj[m]) * sigf(best));
        uint32_t bits = __float_as_uint(f);   // positive float: uint order == float order
        g_scorebits[m] = bits;
        g_label[m] = (uint8_t)lab;
        atomicAdd(&sh[bits >> 20], 1u);
    }
    __syncthreads();
    for (int i = threadIdx.x; i < NBINS; i += blockDim.x) {
        uint32_t v = sh[i];
        if (v) atomicAdd(&g_hist[i], v);
    }

    // ---- last-block round-1 select (256 threads, 16 bins each) ----
    __shared__ uint32_t amLast;
    __threadfence();
    if (threadIdx.x == 0)
        amLast = (atomicAdd(&g_tick1, 1u) == gridDim.x - 1u) ? 1u : 0u;
    __syncthreads();
    if (!amLast) return;

    int t = threadIdx.x;
    __shared__ uint32_t ssum[256];
    volatile uint32_t* vh = g_hist;
    uint32_t h[16];
    uint32_t s = 0;
    int base = t * 16;
#pragma unroll
    for (int k = 0; k < 16; k++) { h[k] = vh[base + k]; s += h[k]; }
    ssum[t] = s;
    __syncthreads();
    for (int off = 1; off < 256; off <<= 1) {
        uint32_t v = (t + off < 256) ? ssum[t + off] : 0u;
        __syncthreads();
        ssum[t] += v;
        __syncthreads();
    }
    uint32_t cum = (t < 255) ? ssum[t + 1] : 0u;   // strictly-above-chunk count
#pragma unroll
    for (int k = 15; k >= 0; k--) {
        uint32_t bc = h[k];
        if (bc > 0 && cum < (uint32_t)TOPK && cum + bc >= (uint32_t)TOPK) {
            g_prefix = (uint32_t)(base + k) << 20;
            g_need   = (uint32_t)TOPK - cum;
        }
        cum += bc;
    }
#pragma unroll
    for (int k = 0; k < 16; k++) g_hist[base + k] = 0;   // ready for round 2
    if (t == 0) { g_cand_cnt = 0; g_tick1 = 0; }
}

// ============================================================================
// K2: refinement hist (next 12 bits); LAST BLOCK: round-2 select -> threshold
// ============================================================================
__global__ void k_hist2(int M) {
    __shared__ uint32_t sh[NBINS];
    for (int i = threadIdx.x; i < NBINS; i += blockDim.x) sh[i] = 0;
    __syncthreads();
    uint32_t pre = g_prefix;   // (bin << 20)
    const uint4* sb4 = (const uint4*)g_scorebits;
    int n4 = M >> 2;
    for (int i = blockIdx.x * blockDim.x + threadIdx.x; i < n4;
         i += gridDim.x * blockDim.x) {
        uint4 v = sb4[i];
        if ((v.x & 0xFFF00000u) == pre) atomicAdd(&sh[(v.x >> 8) & 0xFFFu], 1u);
        if ((v.y & 0xFFF00000u) == pre) atomicAdd(&sh[(v.y >> 8) & 0xFFFu], 1u);
        if ((v.z & 0xFFF00000u) == pre) atomicAdd(&sh[(v.z >> 8) & 0xFFFu], 1u);
        if ((v.w & 0xFFF00000u) == pre) atomicAdd(&sh[(v.w >> 8) & 0xFFFu], 1u);
    }
    if (blockIdx.x == 0 && (int)threadIdx.x < (M & 3)) {
        uint32_t b = g_scorebits[(n4 << 2) + threadIdx.x];
        if ((b & 0xFFF00000u) == pre) atomicAdd(&sh[(b >> 8) & 0xFFFu], 1u);
    }
    __syncthreads();
    for (int i = threadIdx.x; i < NBINS; i += blockDim.x) {
        uint32_t v = sh[i];
        if (v) atomicAdd(&g_hist[i], v);
    }

    // ---- last-block round-2 select (1024 threads, 4 bins each) ----
    __shared__ uint32_t amLast;
    __threadfence();
    if (threadIdx.x == 0)
        amLast = (atomicAdd(&g_tick2, 1u) == gridDim.x - 1u) ? 1u : 0u;
    __syncthreads();
    if (!amLast) return;

    int t = threadIdx.x;
    __shared__ uint32_t ssum[1024];
    volatile uint32_t* vh = g_hist;
    uint32_t h0 = vh[t * 4 + 0];
    uint32_t h1 = vh[t * 4 + 1];
    uint32_t h2 = vh[t * 4 + 2];
    uint32_t h3 = vh[t * 4 + 3];
    ssum[t] = h0 + h1 + h2 + h3;
    uint32_t need = g_need;
    __syncthreads();
    for (int off = 1; off < 1024; off <<= 1) {
        uint32_t v = (t + off < 1024) ? ssum[t + off] : 0u;
        __syncthreads();
        ssum[t] += v;
        __syncthreads();
    }
    uint32_t cum = (t < 1023) ? ssum[t + 1] : 0u;
    uint32_t hh[4] = {h0, h1, h2, h3};
#pragma unroll
    for (int c = 3; c >= 0; c--) {
        uint32_t bc = hh[c];
        if (bc > 0 && cum < need && cum + bc >= need)
            g_prefix = pre | ((uint32_t)(t * 4 + c) << 8);   // final 24-bit threshold
        cum += bc;
    }
    g_hist[t * 4 + 0] = 0;   // restore zero for next replay
    g_hist[t * 4 + 1] = 0;
    g_hist[t * 4 + 2] = 0;
    g_hist[t * 4 + 3] = 0;
    if (t == 0) g_tick2 = 0;
}

// ============================================================================
// K3: gather candidates; LAST BLOCK: rank + fetch + sup-matrix + NMS + output
// ============================================================================
__global__ void k_finish(const float4* __restrict__ boxp,
                         float* __restrict__ out, int out_size, int M) {
    uint32_t T = g_prefix;
    const uint4* sb4 = (const uint4*)g_scorebits;
    int n4 = M >> 2;
    for (int i = blockIdx.x * blockDim.x + threadIdx.x; i < n4;
         i += gridDim.x * blockDim.x) {
        uint4 v = sb4[i];
        uint32_t m0 = (uint32_t)(i << 2);
        uint32_t bb[4] = {v.x, v.y, v.z, v.w};
#pragma unroll
        for (int c = 0; c < 4; c++) {
            if (bb[c] >= T) {
                uint32_t p = atomicAdd(&g_cand_cnt, 1u);
                if (p < CAND_CAP)
                    g_cand[p] = ((unsigned long long)bb[c] << 32) |
                                (unsigned long long)(0xFFFFFFFFu - (m0 + c));
            }
        }
    }
    if (blockIdx.x == 0 && (int)threadIdx.x < (M & 3)) {
        uint32_t m = (uint32_t)((n4 << 2) + threadIdx.x);
        uint32_t b = g_scorebits[m];
        if (b >= T) {
            uint32_t p = atomicAdd(&g_cand_cnt, 1u);
            if (p < CAND_CAP)
                g_cand[p] = ((unsigned long long)b << 32) |
                            (unsigned long long)(0xFFFFFFFFu - m);
        }
    }

    __shared__ uint32_t amLast;
    __threadfence();
    if (threadIdx.x == 0)
        amLast = (atomicAdd(&g_tick3, 1u) == gridDim.x - 1u) ? 1u : 0u;
    __syncthreads();
    if (!amLast) return;

    // ---------------- last block: everything else ----------------
    extern __shared__ char smem[];
    float4* sbox = (float4*)smem;                                  // 16000 B (raw boxes)
    unsigned long long* keys = (unsigned long long*)(sbox + TOPK); // 32768 B
    float* sx1   = (float*)(keys + CAND_CAP);                      // 4000 B each
    float* sy1   = sx1 + TOPK;
    float* sx2   = sy1 + TOPK;
    float* sy2   = sx2 + TOPK;
    float* sarea = sy2 + TOPK;
    float* sscr  = sarea + TOPK;
    int*   slab  = (int*)(sscr + TOPK);
    uint32_t* sup = (uint32_t*)(slab + TOPK);                      // 32*1025*4 B
    __shared__ uint32_t rowNZ[32];
    __shared__ uint32_t keep[32];

    int t = threadIdx.x;
    uint32_t n = g_cand_cnt;
    if (n > CAND_CAP) n = CAND_CAP;

    for (uint32_t i = t; i < n; i += 1024) keys[i] = g_cand[i];
    if (t < 32) rowNZ[t] = 0;
    __syncthreads();

    // exact rank by counting (n ~ 1000-1100); write directly to rank slot
    for (uint32_t c = t; c < n; c += 1024) {
        unsigned long long k = keys[c];
        int r = 0;
        uint32_t j = 0;
        for (; j + 4 <= n; j += 4) {
            r += (keys[j + 0] > k);
            r += (keys[j + 1] > k);
            r += (keys[j + 2] > k);
            r += (keys[j + 3] > k);
        }
        for (; j < n; j++) r += (keys[j] > k);
        if (r < TOPK) {
            uint32_t idx = 0xFFFFFFFFu - (uint32_t)(k & 0xFFFFFFFFull);
            int lb = (int)g_label[idx];
            float4 b = boxp[idx];
            float off = (float)lb * CLSOFF;
            float x1 = b.x + off, y1 = b.y + off;
            float x2 = b.z + off, y2 = b.w + off;
            sbox[r] = b;
            sscr[r] = __uint_as_float((uint32_t)(k >> 32));
            slab[r] = lb;
            sx1[r] = x1; sy1[r] = y1; sx2[r] = x2; sy2[r] = y2;
            sarea[r] = fmaxf(x2 - x1, 0.0f) * fmaxf(y2 - y1, 0.0f);
        }
    }
    __syncthreads();

    // conf mask -> keep words
    if (t < 32) {
        uint32_t kw = 0;
        for (int b = 0; b < 32; b++) {
            int j = t * 32 + b;
            if (j < TOPK && sscr[j] > CONF) kw |= (1u << b);
        }
        keep[t] = kw;
    }

    // suppression matrix: warp w owns j-word w; lanes sweep rows
    int w = t >> 5;
    int lane = t & 31;
    int jbase = w * 32;
    for (int iter = 0; iter < 32; iter++) {
        int i = iter * 32 + lane;
        uint32_t bits = 0;
        if (i < TOPK && jbase < i) {
            int lb = slab[i];
            float ix1 = sx1[i], iy1 = sy1[i], ix2 = sx2[i], iy2 = sy2[i];
            float ia = sarea[i];
            int jend = jbase + 32; if (jend > i) jend = i;
            for (int j = jbase; j < jend; j++) {
                if (slab[j] == lb) {   // cross-class IoU is exactly 0 (offset geometry)
                    float xx1 = fmaxf(ix1, sx1[j]);
                    float yy1 = fmaxf(iy1, sy1[j]);
                    float xx2 = fminf(ix2, sx2[j]);
                    float yy2 = fminf(iy2, sy2[j]);
                    float inter = fmaxf(xx2 - xx1, 0.0f) * fmaxf(yy2 - yy1, 0.0f);
                    float iou = inter / (ia + sarea[j] - inter + 1e-9f);
                    if (iou > NMSTH) bits |= (1u << (j - jbase));
                }
            }
        }
        if (i < TOPK) {
            sup[w * SUPSTRIDE + i] = bits;
            if (bits) atomicOr(&rowNZ[i >> 5], 1u << (i & 31));
        }
    }
    __syncthreads();

    // sparse serial sweep: only contested rows; warp 0, lane = keep-word owner
    if (t < 32) {
        uint32_t kw = keep[lane];
        for (int w2 = 0; w2 < 32; w2++) {
            uint32_t rb = rowNZ[w2];
            while (rb) {
                int b = __ffs(rb) - 1;
                rb &= rb - 1;
                int i = w2 * 32 + b;
                int iw = i >> 5;
                uint32_t ib = (uint32_t)(i & 31);
                uint32_t ltm = (lane < iw) ? 0xFFFFFFFFu
                             : ((lane == iw) ? ((1u << ib) - 1u) : 0u);
                uint32_t v = sup[lane * SUPSTRIDE + i] & kw & ltm;
                if (__any_sync(0xFFFFFFFFu, v != 0u)) {
                    if (lane == iw) kw &= ~(1u << ib);
                }
            }
        }
        keep[lane] = kw;
    }
    __syncthreads();

    if (t < TOPK) {
        float kf = ((keep[t >> 5] >> (t & 31)) & 1u) ? 1.0f : 0.0f;
        float4 b = sbox[t];            // raw (un-offset) box, matches reference
        out[t * 5 + 0] = sscr[t] * kf;
        out[t * 5 + 1] = b.x * kf;
        out[t * 5 + 2] = b.y * kf;
        out[t * 5 + 3] = b.z * kf;
        out[t * 5 + 4] = b.w * kf;
        if (out_size >= 6000) out[5000 + t] = (float)slab[t];
        if (out_size >= 7000) out[6000 + t] = kf;
    }
    if (t == 0) g_tick3 = 0;
}

// ---------------- launch (3 kernels total) ----------------
extern "C" void kernel_launch(void* const* d_in, const int* in_sizes, int n_in,
                              void* d_out, int out_size) {
    const float* obj   = (const float*)d_in[0];
    const float* cls   = (const float*)d_in[1];
    const float4* boxp = (const float4*)d_in[2];
    float* out = (float*)d_out;
    int M = in_sizes[0];
    if (M > MAXM) M = MAXM;
    (void)n_in;

    const int FIN_SMEM = (int)(TOPK * sizeof(float4))                 // sbox
                       + (int)(CAND_CAP * sizeof(unsigned long long)) // keys
                       + (int)(TOPK * 6 * sizeof(float))              // x1..area,score
                       + (int)(TOPK * sizeof(int))                    // labels
                       + (int)(32 * SUPSTRIDE * sizeof(uint32_t));    // sup matrix
    cudaFuncSetAttribute(k_finish, cudaFuncAttributeMaxDynamicSharedMemorySize,
                         FIN_SMEM);

    int gs = (M + 255) / 256;
    int n4 = M >> 2;
    int gb = (n4 + 1023) / 1024;
    if (gb > 148) gb = 148;
    if (gb < 1) gb = 1;

    k_score<<<gs, 256>>>(obj, cls, M);
    k_hist2<<<gb, 1024>>>(M);
    k_finish<<<gb, 1024, FIN_SMEM>>>(boxp, out, out_size, M);
}

// round 4
// speedup vs baseline: 2.3827x; 2.3827x over previous
#include <cuda_runtime.h>
#include <stdint.h>

// ---------------- problem constants ----------------
#define MAXM      300000
#define NCLS      80
#define TOPK      1000
#define CONF      0.001f
#define NMSTH     0.5f
#define CLSOFF    4096.0f
#define CAND_CAP  4096
#define NBINS     4096
#define NLCAP     384      // contested rows staged in static smem

// ---------------- device scratch (zero-initialized at load) ----------------
__device__ uint32_t g_scorebits[MAXM];
__device__ uint32_t g_hist[NBINS];    // returned to zero by the select kernels
__device__ uint32_t g_prefix;
__device__ uint32_t g_need;
__device__ uint32_t g_cand_cnt;
__device__ unsigned long long g_cand[CAND_CAP];
// ranked top-k data
__device__ float   g_x1[TOPK], g_y1[TOPK], g_x2[TOPK], g_y2[TOPK];
__device__ float   g_area[TOPK], g_scr[TOPK];
__device__ float4  g_box[TOPK];
__device__ int     g_lab[TOPK];
__device__ uint32_t g_sup[TOPK * 32];  // fully overwritten each replay
__device__ uint32_t g_rowNZ[32];       // reset by k_sel2
__device__ uint32_t g_keep0[32];       // reset by k_sel2

__device__ __forceinline__ float sigf(float x) {
    return 1.0f / (1.0f + expf(-x));
}

// ============================================================================
// K1: max-logit (fmaxf tree, NO argmax) + exact fused score + 12-bit hist
// ============================================================================
__global__ void k_score(const float* __restrict__ obj,
                        const float* __restrict__ cls, int M) {
    __shared__ uint32_t sh[NBINS];
    for (int i = threadIdx.x; i < NBINS; i += blockDim.x) sh[i] = 0;
    __syncthreads();

    int m = blockIdx.x * blockDim.x + threadIdx.x;
    if (m < M) {
        const float4* c4 = (const float4*)(cls + (size_t)m * NCLS);
        float q[20];
#pragma unroll
        for (int i = 0; i < 20; i++) {
            float4 v = c4[i];
            q[i] = fmaxf(fmaxf(v.x, v.y), fmaxf(v.z, v.w));
        }
        // tree reduce 20 -> 1 (independent FMNMX, good ILP)
#pragma unroll
        for (int i = 0; i < 10; i++) q[i] = fmaxf(q[i], q[i + 10]);
#pragma unroll
        for (int i = 0; i < 5; i++)  q[i] = fmaxf(q[i], q[i + 5]);
        float best = fmaxf(fmaxf(q[0], q[1]), fmaxf(fmaxf(q[2], q[3]), q[4]));
        // monotone: max_c sqrt(sig(o)*sig(c)) == sqrt(sig(o)*sig(max_c))
        float f = sqrtf(sigf(obj[m]) * sigf(best));
        uint32_t bits = __float_as_uint(f);   // positive: uint order == float order
        g_scorebits[m] = bits;
        atomicAdd(&sh[bits >> 20], 1u);
    }
    __syncthreads();
    for (int i = threadIdx.x; i < NBINS; i += blockDim.x) {
        uint32_t v = sh[i];
        if (v) atomicAdd(&g_hist[i], v);
    }
}

// ============================================================================
// K2: round-1 select (top 12 bits) — sets prefix/need, zeros hist, resets cand
// ============================================================================
__global__ void k_sel1() {
    __shared__ uint32_t ssum[1024];
    int t = threadIdx.x;
    uint32_t h0 = g_hist[t * 4 + 0];
    uint32_t h1 = g_hist[t * 4 + 1];
    uint32_t h2 = g_hist[t * 4 + 2];
    uint32_t h3 = g_hist[t * 4 + 3];
    ssum[t] = h0 + h1 + h2 + h3;
    __syncthreads();
    for (int off = 1; off < 1024; off <<= 1) {
        uint32_t v = (t + off < 1024) ? ssum[t + off] : 0u;
        __syncthreads();
        ssum[t] += v;
        __syncthreads();
    }
    uint32_t cum = (t < 1023) ? ssum[t + 1] : 0u;   // strictly-above count
    uint32_t hh[4] = {h0, h1, h2, h3};
#pragma unroll
    for (int c = 3; c >= 0; c--) {
        uint32_t bc = hh[c];
        if (bc > 0 && cum < (uint32_t)TOPK && cum + bc >= (uint32_t)TOPK) {
            g_prefix = (uint32_t)(t * 4 + c) << 20;
            g_need   = (uint32_t)TOPK - cum;
        }
        cum += bc;
    }
    g_hist[t * 4 + 0] = 0;
    g_hist[t * 4 + 1] = 0;
    g_hist[t * 4 + 2] = 0;
    g_hist[t * 4 + 3] = 0;
    if (t == 0) g_cand_cnt = 0;
}

// ============================================================================
// K3: refinement hist over next 12 bits (prefix-matching elements only)
// ============================================================================
__global__ void k_hist2(int M) {
    __shared__ uint32_t sh[NBINS];
    for (int i = threadIdx.x; i < NBINS; i += blockDim.x) sh[i] = 0;
    __syncthreads();
    uint32_t pre = g_prefix;
    const uint4* sb4 = (const uint4*)g_scorebits;
    int n4 = M >> 2;
    for (int i = blockIdx.x * blockDim.x + threadIdx.x; i < n4;
         i += gridDim.x * blockDim.x) {
        uint4 v = sb4[i];
        if ((v.x & 0xFFF00000u) == pre) atomicAdd(&sh[(v.x >> 8) & 0xFFFu], 1u);
        if ((v.y & 0xFFF00000u) == pre) atomicAdd(&sh[(v.y >> 8) & 0xFFFu], 1u);
        if ((v.z & 0xFFF00000u) == pre) atomicAdd(&sh[(v.z >> 8) & 0xFFFu], 1u);
        if ((v.w & 0xFFF00000u) == pre) atomicAdd(&sh[(v.w >> 8) & 0xFFFu], 1u);
    }
    if (blockIdx.x == 0 && (int)threadIdx.x < (M & 3)) {
        uint32_t b = g_scorebits[(n4 << 2) + threadIdx.x];
        if ((b & 0xFFF00000u) == pre) atomicAdd(&sh[(b >> 8) & 0xFFFu], 1u);
    }
    __syncthreads();
    for (int i = threadIdx.x; i < NBINS; i += blockDim.x) {
        uint32_t v = sh[i];
        if (v) atomicAdd(&g_hist[i], v);
    }
}

// ============================================================================
// K4: round-2 select -> final 24-bit threshold; resets hist/rowNZ/keep0
// ============================================================================
__global__ void k_sel2() {
    __shared__ uint32_t ssum[1024];
    int t = threadIdx.x;
    uint32_t pre  = g_prefix;
    uint32_t need = g_need;
    uint32_t h0 = g_hist[t * 4 + 0];
    uint32_t h1 = g_hist[t * 4 + 1];
    uint32_t h2 = g_hist[t * 4 + 2];
    uint32_t h3 = g_hist[t * 4 + 3];
    ssum[t] = h0 + h1 + h2 + h3;
    __syncthreads();
    for (int off = 1; off < 1024; off <<= 1) {
        uint32_t v = (t + off < 1024) ? ssum[t + off] : 0u;
        __syncthreads();
        ssum[t] += v;
        __syncthreads();
    }
    uint32_t cum = (t < 1023) ? ssum[t + 1] : 0u;
    uint32_t hh[4] = {h0, h1, h2, h3};
#pragma unroll
    for (int c = 3; c >= 0; c--) {
        uint32_t bc = hh[c];
        if (bc > 0 && cum < need && cum + bc >= need)
            g_prefix = pre | ((uint32_t)(t * 4 + c) << 8);  // 24-bit threshold
        cum += bc;
    }
    g_hist[t * 4 + 0] = 0;
    g_hist[t * 4 + 1] = 0;
    g_hist[t * 4 + 2] = 0;
    g_hist[t * 4 + 3] = 0;
    if (t < 32) { g_rowNZ[t] = 0; g_keep0[t] = 0; }
}

// ============================================================================
// K5: gather (bits, idx) with bits >= threshold
// ============================================================================
__global__ void k_gather(int M) {
    uint32_t T = g_prefix;
    const uint4* sb4 = (const uint4*)g_scorebits;
    int n4 = M >> 2;
    for (int i = blockIdx.x * blockDim.x + threadIdx.x; i < n4;
         i += gridDim.x * blockDim.x) {
        uint4 v = sb4[i];
        uint32_t m0 = (uint32_t)(i << 2);
        uint32_t bb[4] = {v.x, v.y, v.z, v.w};
#pragma unroll
        for (int c = 0; c < 4; c++) {
            if (bb[c] >= T) {
                uint32_t p = atomicAdd(&g_cand_cnt, 1u);
                if (p < CAND_CAP)
                    g_cand[p] = ((unsigned long long)bb[c] << 32) |
                                (unsigned long long)(0xFFFFFFFFu - (m0 + c));
            }
        }
    }
    if (blockIdx.x == 0 && (int)threadIdx.x < (M & 3)) {
        uint32_t m = (uint32_t)((n4 << 2) + threadIdx.x);
        uint32_t b = g_scorebits[m];
        if (b >= T) {
            uint32_t p = atomicAdd(&g_cand_cnt, 1u);
            if (p < CAND_CAP)
                g_cand[p] = ((unsigned long long)b << 32) |
                            (unsigned long long)(0xFFFFFFFFu - m);
        }
    }
}

// ============================================================================
// K6: parallel rank-by-count + label recompute + box fetch (16 blocks x 256)
// ============================================================================
__global__ void k_rank(const float* __restrict__ cls,
                       const float4* __restrict__ boxp) {
    __shared__ unsigned long long keys[CAND_CAP];
    int t = threadIdx.x;
    uint32_t n = g_cand_cnt;
    if (n > CAND_CAP) n = CAND_CAP;
    uint32_t c = blockIdx.x * 256 + t;
    if (blockIdx.x * 256 >= n) return;   // block-uniform early exit

    for (uint32_t i = t; i < n; i += 256) keys[i] = g_cand[i];
    __syncthreads();

    if (c < n) {
        unsigned long long k = keys[c];
        int r = 0;
        uint32_t j = 0;
        for (; j + 4 <= n; j += 4) {
            r += (keys[j + 0] > k);
            r += (keys[j + 1] > k);
            r += (keys[j + 2] > k);
            r += (keys[j + 3] > k);
        }
        for (; j < n; j++) r += (keys[j] > k);
        if (r < TOPK) {
            uint32_t idx = 0xFFFFFFFFu - (uint32_t)(k & 0xFFFFFFFFull);
            // recompute argmax label (first max, jax semantics) for this anchor
            const float* cr = cls + (size_t)idx * NCLS;
            float best = -1e30f;
            int lab = 0;
#pragma unroll
            for (int q = 0; q < NCLS; q++) {
                float v = __ldg(cr + q);
                if (v > best) { best = v; lab = q; }
            }
            float scr = __uint_as_float((uint32_t)(k >> 32));
            float4 b = boxp[idx];
            float off = (float)lab * CLSOFF;
            float x1 = b.x + off, y1 = b.y + off;
            float x2 = b.z + off, y2 = b.w + off;
            g_box[r] = b;
            g_scr[r] = scr;
            g_lab[r] = lab;
            g_x1[r] = x1; g_y1[r] = y1; g_x2[r] = x2; g_y2[r] = y2;
            g_area[r] = fmaxf(x2 - x1, 0.0f) * fmaxf(y2 - y1, 0.0f);
            if (scr > CONF) atomicOr(&g_keep0[r >> 5], 1u << (r & 31));
        }
    }
}

// ============================================================================
// K7: suppression bit-matrix, grid-wide (32 blocks x 1024), boxes in smem
// ============================================================================
__global__ void k_sup() {
    __shared__ float sx1[TOPK], sy1[TOPK], sx2[TOPK], sy2[TOPK], sarea[TOPK];
    __shared__ int   slab[TOPK];
    int t = threadIdx.x;
    for (int i = t; i < TOPK; i += 1024) {
        sx1[i] = g_x1[i]; sy1[i] = g_y1[i];
        sx2[i] = g_x2[i]; sy2[i] = g_y2[i];
        sarea[i] = g_area[i]; slab[i] = g_lab[i];
    }
    __syncthreads();

    int w = t >> 5;          // j-word
    int lane = t & 31;       // row within this block's 32-row band
    int i = blockIdx.x * 32 + lane;
    int jbase = w * 32;
    uint32_t bits = 0;
    if (i < TOPK && jbase < i) {
        int lb = slab[i];
        float ix1 = sx1[i], iy1 = sy1[i], ix2 = sx2[i], iy2 = sy2[i];
        float ia = sarea[i];
        int jend = jbase + 32; if (jend > i) jend = i;
        for (int j = jbase; j < jend; j++) {
            if (slab[j] == lb) {   // cross-class IoU is exactly 0 (offset geometry)
                float xx1 = fmaxf(ix1, sx1[j]);
                float yy1 = fmaxf(iy1, sy1[j]);
                float xx2 = fminf(ix2, sx2[j]);
                float yy2 = fminf(iy2, sy2[j]);
                float inter = fmaxf(xx2 - xx1, 0.0f) * fmaxf(yy2 - yy1, 0.0f);
                float iou = inter / (ia + sarea[j] - inter + 1e-9f);
                if (iou > NMSTH) bits |= (1u << (j - jbase));
            }
        }
    }
    if (i < TOPK) {
        g_sup[i * 32 + w] = bits;
        if (bits) atomicOr(&g_rowNZ[i >> 5], 1u << (i & 31));
    }
}

// ============================================================================
// K8: sparse greedy sweep over contested rows + output (1 block, static smem)
// ============================================================================
__global__ void k_nms(float* __restrict__ out, int out_size) {
    __shared__ uint32_t srow[NLCAP * 32];   // 48 KB: staged contested rows
    __shared__ int      list[1024];
    __shared__ int      nlist;
    __shared__ uint32_t keep[32];
    __shared__ uint32_t rnz[32];

    int t = threadIdx.x;
    int lane = t & 31;
    if (t < 32) { keep[t] = g_keep0[t]; rnz[t] = g_rowNZ[t]; }
    __syncthreads();

    // warp 0: build ascending list of contested rows
    if (t < 32) {
        int cnt = 0;
        for (int w2 = 0; w2 < 32; w2++) {
            uint32_t rb = rnz[w2];
            int bit = (rb >> lane) & 1;
            uint32_t bal = __ballot_sync(0xFFFFFFFFu, bit);
            if (bit) {
                int pos = cnt + __popc(bal & ((1u << lane) - 1u));
                list[pos] = w2 * 32 + lane;
            }
            cnt += __popc(bal);
        }
        if (lane == 0) nlist = cnt;
    }
    __syncthreads();

    // stage contested rows (first NLCAP) into smem; warp w loads rows w, w+32, ...
    int nl = nlist;
    for (int l = t >> 5; l < nl && l < NLCAP; l += 32)
        srow[l * 32 + lane] = g_sup[list[l] * 32 + lane];
    __syncthreads();

    // warp 0: serial greedy sweep, lane owns keep-word lane
    if (t < 32) {
        uint32_t kw = keep[lane];
        for (int l = 0; l < nl; l++) {
            int i = list[l];
            int iw = i >> 5;
            uint32_t ib = (uint32_t)(i & 31);
            uint32_t ltm = (lane < iw) ? 0xFFFFFFFFu
                         : ((lane == iw) ? ((1u << ib) - 1u) : 0u);
            uint32_t row = (l < NLCAP) ? srow[l * 32 + lane]
                                       : g_sup[i * 32 + lane];
            uint32_t v = row & kw & ltm;
            if (__any_sync(0xFFFFFFFFu, v != 0u)) {
                if (lane == iw) kw &= ~(1u << ib);
            }
        }
        keep[lane] = kw;
    }
    __syncthreads();

    if (t < TOPK) {
        float kf = ((keep[t >> 5] >> (t & 31)) & 1u) ? 1.0f : 0.0f;
        float4 b = g_box[t];   // raw (un-offset) box, matches reference
        out[t * 5 + 0] = g_scr[t] * kf;
        out[t * 5 + 1] = b.x * kf;
        out[t * 5 + 2] = b.y * kf;
        out[t * 5 + 3] = b.z * kf;
        out[t * 5 + 4] = b.w * kf;
        if (out_size >= 6000) out[5000 + t] = (float)g_lab[t];
        if (out_size >= 7000) out[6000 + t] = kf;
    }
}

// ---------------- launch (8 kernels) ----------------
extern "C" void kernel_launch(void* const* d_in, const int* in_sizes, int n_in,
                              void* d_out, int out_size) {
    const float* obj   = (const float*)d_in[0];
    const float* cls   = (const float*)d_in[1];
    const float4* boxp = (const float4*)d_in[2];
    float* out = (float*)d_out;
    int M = in_sizes[0];
    if (M > MAXM) M = MAXM;
    (void)n_in;

    int gs = (M + 255) / 256;
    int n4 = M >> 2;
    int gb = (n4 + 1023) / 1024;
    if (gb > 148) gb = 148;
    if (gb < 1) gb = 1;

    k_score<<<gs, 256>>>(obj, cls, M);
    k_sel1<<<1, 1024>>>();
    k_hist2<<<gb, 1024>>>(M);
    k_sel2<<<1, 1024>>>();
    k_gather<<<gb, 1024>>>(M);
    k_rank<<<16, 256>>>(cls, boxp);
    k_sup<<<(TOPK + 31) / 32, 1024>>>();
    k_nms<<<1, 1024>>>(out, out_size);
}